// round 1
// baseline (speedup 1.0000x reference)
#include <cuda_runtime.h>
#include <cuda_bf16.h>
#include <math_constants.h>

// Attention: out = softmax(Q@K / 8 + mask) @ V
// q: [B,H,S,D] f32, k: [B,H,D,S] f32 (pre-transposed), v: [B,H,S,D] f32
// mask: [B,1,1,S] f32, out: [B,H,S,D] f32
// B=4 H=16 S=2048 D=64

#define B_ 4
#define H_ 16
#define S_ 2048
#define D_ 64
#define BM 64      // query rows per CTA
#define BN 64      // key cols per tile
#define NTHREADS 128
#define LOG2E 1.4426950408889634f

struct Smem {
    float Qt[D_][BM + 4];   // [d][row], padded
    float Ksm[D_][BN];      // [d][t]
    float Vsm[BN][D_];      // [t][d]
    float Pt[BN][BM + 4];   // [j][row], padded
};

__global__ void __launch_bounds__(NTHREADS)
attn_kernel(const float* __restrict__ q, const float* __restrict__ k,
            const float* __restrict__ v, const float* __restrict__ mask,
            float* __restrict__ out)
{
    extern __shared__ char smem_raw[];
    Smem& sm = *reinterpret_cast<Smem*>(smem_raw);

    const int tid = threadIdx.x;
    const int tx  = tid & 15;      // 0..15 -> 4 cols each
    const int ty  = tid >> 4;      // 0..7  -> 8 rows each
    const int bh  = blockIdx.y;    // 0..63
    const int b   = bh >> 4;       // H=16
    const int qrow0 = blockIdx.x * BM;

    const float* qbase = q + (size_t)bh * S_ * D_;
    const float* kbase = k + (size_t)bh * D_ * S_;
    const float* vbase = v + (size_t)bh * S_ * D_;
    const float* mbase = mask + (size_t)b * S_;

    // ---- load Q tile, transposed into smem: Qt[d][row] ----
#pragma unroll
    for (int i = 0; i < 8; i++) {
        int lin = (tid + i * NTHREADS) * 4;       // over [row][d] 64x64
        int row = lin >> 6;
        int d0  = lin & 63;
        float4 t = *reinterpret_cast<const float4*>(
            qbase + (size_t)(qrow0 + row) * D_ + d0);
        sm.Qt[d0 + 0][row] = t.x;
        sm.Qt[d0 + 1][row] = t.y;
        sm.Qt[d0 + 2][row] = t.z;
        sm.Qt[d0 + 3][row] = t.w;
    }

    float o[8][4];
    float mrun[8], lrun[8];
#pragma unroll
    for (int r = 0; r < 8; r++) {
        mrun[r] = -CUDART_INF_F;
        lrun[r] = 0.0f;
#pragma unroll
        for (int c = 0; c < 4; c++) o[r][c] = 0.0f;
    }

    for (int t0 = 0; t0 < S_; t0 += BN) {
        // ---- load K tile [d][t] and V tile [t][d] ----
        __syncthreads();   // previous GEMMs done with Ksm/Vsm
#pragma unroll
        for (int i = 0; i < 8; i++) {
            int lin = (tid + i * NTHREADS) * 4;
            int r0  = lin >> 6;
            int c0  = lin & 63;
            // K: row d=r0, cols t0+c0..+3 (contiguous in gmem)
            *reinterpret_cast<float4*>(&sm.Ksm[r0][c0]) =
                *reinterpret_cast<const float4*>(kbase + (size_t)r0 * S_ + t0 + c0);
            // V: row t=t0+r0, dims c0..+3
            *reinterpret_cast<float4*>(&sm.Vsm[r0][c0]) =
                *reinterpret_cast<const float4*>(vbase + (size_t)(t0 + r0) * D_ + c0);
        }
        __syncthreads();

        // ---- GEMM1: s[8][4] = Q[rows ty*8..][*] dot K[*][tx*4..] ----
        float s[8][4];
#pragma unroll
        for (int r = 0; r < 8; r++)
#pragma unroll
            for (int c = 0; c < 4; c++) s[r][c] = 0.0f;

#pragma unroll 8
        for (int d = 0; d < D_; d++) {
            float4 kf = *reinterpret_cast<const float4*>(&sm.Ksm[d][tx * 4]);
            float4 qa = *reinterpret_cast<const float4*>(&sm.Qt[d][ty * 8]);
            float4 qb = *reinterpret_cast<const float4*>(&sm.Qt[d][ty * 8 + 4]);
            const float qr[8] = {qa.x, qa.y, qa.z, qa.w, qb.x, qb.y, qb.z, qb.w};
            const float kc[4] = {kf.x, kf.y, kf.z, kf.w};
#pragma unroll
            for (int r = 0; r < 8; r++)
#pragma unroll
                for (int c = 0; c < 4; c++)
                    s[r][c] = fmaf(qr[r], kc[c], s[r][c]);
        }

        // ---- softmax (online) ----
        float4 mf4 = *reinterpret_cast<const float4*>(mbase + t0 + tx * 4);
        const float mf[4] = {mf4.x, mf4.y, mf4.z, mf4.w};

#pragma unroll
        for (int r = 0; r < 8; r++) {
            float x[4];
#pragma unroll
            for (int c = 0; c < 4; c++)
                x[c] = s[r][c] * 0.125f + mf[c];

            float rmax = fmaxf(fmaxf(x[0], x[1]), fmaxf(x[2], x[3]));
#pragma unroll
            for (int off = 1; off < 16; off <<= 1)
                rmax = fmaxf(rmax, __shfl_xor_sync(0xffffffffu, rmax, off));

            float nm = fmaxf(mrun[r], rmax);
            float p[4], psum = 0.0f;
#pragma unroll
            for (int c = 0; c < 4; c++) {
                p[c] = exp2f((x[c] - nm) * LOG2E);
                psum += p[c];
            }
#pragma unroll
            for (int off = 1; off < 16; off <<= 1)
                psum += __shfl_xor_sync(0xffffffffu, psum, off);

            float corr = exp2f((mrun[r] - nm) * LOG2E);
            lrun[r] = lrun[r] * corr + psum;
            mrun[r] = nm;
#pragma unroll
            for (int c = 0; c < 4; c++) {
                o[r][c] *= corr;
                sm.Pt[tx * 4 + c][ty * 8 + r] = p[c];
            }
        }
        __syncthreads();   // Pt visible to all

        // ---- GEMM2: o += P[rows][j] * V[j][dims] ----
#pragma unroll 8
        for (int j = 0; j < BN; j++) {
            float4 vf = *reinterpret_cast<const float4*>(&sm.Vsm[j][tx * 4]);
            float4 pa = *reinterpret_cast<const float4*>(&sm.Pt[j][ty * 8]);
            float4 pb = *reinterpret_cast<const float4*>(&sm.Pt[j][ty * 8 + 4]);
            const float pr[8] = {pa.x, pa.y, pa.z, pa.w, pb.x, pb.y, pb.z, pb.w};
            const float vc[4] = {vf.x, vf.y, vf.z, vf.w};
#pragma unroll
            for (int r = 0; r < 8; r++)
#pragma unroll
                for (int c = 0; c < 4; c++)
                    o[r][c] = fmaf(pr[r], vc[c], o[r][c]);
        }
    }

    // ---- epilogue: normalize and store ----
#pragma unroll
    for (int r = 0; r < 8; r++) {
        float inv = 1.0f / lrun[r];
        float4 res;
        res.x = o[r][0] * inv;
        res.y = o[r][1] * inv;
        res.z = o[r][2] * inv;
        res.w = o[r][3] * inv;
        *reinterpret_cast<float4*>(
            out + ((size_t)bh * S_ + qrow0 + ty * 8 + r) * D_ + tx * 4) = res;
    }
}

extern "C" void kernel_launch(void* const* d_in, const int* in_sizes, int n_in,
                              void* d_out, int out_size)
{
    const float* q    = (const float*)d_in[0];
    const float* k    = (const float*)d_in[1];
    const float* v    = (const float*)d_in[2];
    const float* mask = (const float*)d_in[3];
    float* out        = (float*)d_out;

    size_t smem = sizeof(Smem);
    cudaFuncSetAttribute(attn_kernel, cudaFuncAttributeMaxDynamicSharedMemorySize,
                         (int)smem);

    dim3 grid(S_ / BM, B_ * H_);
    attn_kernel<<<grid, NTHREADS, smem>>>(q, k, v, mask, out);
}

// round 3
// speedup vs baseline: 5.2578x; 5.2578x over previous
#include <cuda_runtime.h>
#include <cuda_fp16.h>
#include <cstdint>

// out = softmax(Q@K / 8 + mask) @ V
// q: [B,H,S,D] f32, k: [B,H,D,S] f32 (pre-transposed), v: [B,H,S,D] f32
// mask: [B,1,1,S] f32, out: [B,H,S,D] f32.  B=4 H=16 S=2048 D=64
// fp16 tensor cores (mma.m16n8k16), fp32 accumulate, online softmax.

#define B_ 4
#define H_ 16
#define S_ 2048
#define D_ 64
#define BM 128          // query rows per CTA
#define BN 64           // keys per tile
#define NTHREADS 128
#define KST 72          // smem row stride in halfs (pad for bank-free ldmatrix)
#define LOG2E 1.4426950408889634f
#define SCALE_L2 (0.125f * LOG2E)

__device__ __forceinline__ uint32_t smem_u32(const void* p) {
    return (uint32_t)__cvta_generic_to_shared(p);
}

__device__ __forceinline__ void ldsm_x4(uint32_t r[4], uint32_t addr) {
    asm volatile("ldmatrix.sync.aligned.m8n8.x4.shared.b16 {%0,%1,%2,%3}, [%4];"
                 : "=r"(r[0]), "=r"(r[1]), "=r"(r[2]), "=r"(r[3]) : "r"(addr));
}
__device__ __forceinline__ void ldsm_x4_t(uint32_t r[4], uint32_t addr) {
    asm volatile("ldmatrix.sync.aligned.m8n8.x4.trans.shared.b16 {%0,%1,%2,%3}, [%4];"
                 : "=r"(r[0]), "=r"(r[1]), "=r"(r[2]), "=r"(r[3]) : "r"(addr));
}
__device__ __forceinline__ void mma16816(float d[4], const uint32_t a[4],
                                         const uint32_t b0, const uint32_t b1) {
    asm volatile(
        "mma.sync.aligned.m16n8k16.row.col.f32.f16.f16.f32 "
        "{%0,%1,%2,%3},{%4,%5,%6,%7},{%8,%9},{%0,%1,%2,%3};"
        : "+f"(d[0]), "+f"(d[1]), "+f"(d[2]), "+f"(d[3])
        : "r"(a[0]), "r"(a[1]), "r"(a[2]), "r"(a[3]), "r"(b0), "r"(b1));
}
__device__ __forceinline__ float ex2(float x) {
    float r;
    asm("ex2.approx.ftz.f32 %0, %1;" : "=f"(r) : "f"(x));
    return r;
}

__global__ void __launch_bounds__(NTHREADS)
attn_kernel(const float* __restrict__ q, const float* __restrict__ k,
            const float* __restrict__ v, const float* __restrict__ mask,
            float* __restrict__ out)
{
    __shared__ __half Qs[BM * KST];   // [128][72]
    __shared__ __half Ks[BN * KST];   // [64][72]  (d-major: [d][t])
    __shared__ __half Vs[BN * KST];   // [64][72]  (t-major: [t][d])

    const int tid  = threadIdx.x;
    const int lane = tid & 31;
    const int warp = tid >> 5;
    const int bh   = blockIdx.y;
    const int b    = bh >> 4;          // H=16
    const int qrow0 = blockIdx.x * BM;

    const float* qbase = q + (size_t)bh * S_ * D_;
    const float* kbase = k + (size_t)bh * D_ * S_;
    const float* vbase = v + (size_t)bh * S_ * D_;
    const float* mbase = mask + (size_t)b * S_;

    // ---- stage Q (f32 -> f16), [row][d], row stride KST ----
#pragma unroll
    for (int i = 0; i < 16; i++) {
        int idx = tid + i * NTHREADS;          // over 128x16 float4s
        int row = idx >> 4;
        int d4  = (idx & 15) * 4;
        float4 t = *reinterpret_cast<const float4*>(
            qbase + (size_t)(qrow0 + row) * D_ + d4);
        __half2 h0 = __floats2half2_rn(t.x, t.y);
        __half2 h1 = __floats2half2_rn(t.z, t.w);
        uint2 u; u.x = *(uint32_t*)&h0; u.y = *(uint32_t*)&h1;
        *reinterpret_cast<uint2*>(&Qs[row * KST + d4]) = u;
    }
    __syncthreads();

    // ---- load Q A-fragments into regs (per warp: rows warp*32 .. +31) ----
    // qa[mt][kt][4]: m-tile mt (16 rows), k-step kt (16 d)
    uint32_t qa[2][4][4];
    const int ldrow = lane & 15;
    const int ldcol8 = (lane >> 4) * 8;
#pragma unroll
    for (int mt = 0; mt < 2; mt++)
#pragma unroll
        for (int kt = 0; kt < 4; kt++) {
            uint32_t a = smem_u32(
                &Qs[(warp * 32 + mt * 16 + ldrow) * KST + kt * 16 + ldcol8]);
            ldsm_x4(qa[mt][kt], a);
        }

    float o[2][8][4];
    float mrun[2][2], lrun[2][2];
#pragma unroll
    for (int mt = 0; mt < 2; mt++) {
        mrun[mt][0] = mrun[mt][1] = -1e30f;
        lrun[mt][0] = lrun[mt][1] = 0.0f;
#pragma unroll
        for (int nt = 0; nt < 8; nt++)
#pragma unroll
            for (int j = 0; j < 4; j++) o[mt][nt][j] = 0.0f;
    }

    for (int t0 = 0; t0 < S_; t0 += BN) {
        __syncthreads();   // protect K/V from previous iteration's reads
        // ---- stage K: gmem [d][t] -> smem [d][t] halfs ----
#pragma unroll
        for (int i = 0; i < 8; i++) {
            int idx = tid + i * NTHREADS;      // over 64x16 float4s
            int d  = idx >> 4;
            int t4 = (idx & 15) * 4;
            float4 f = *reinterpret_cast<const float4*>(
                kbase + (size_t)d * S_ + t0 + t4);
            __half2 h0 = __floats2half2_rn(f.x, f.y);
            __half2 h1 = __floats2half2_rn(f.z, f.w);
            uint2 u; u.x = *(uint32_t*)&h0; u.y = *(uint32_t*)&h1;
            *reinterpret_cast<uint2*>(&Ks[d * KST + t4]) = u;
        }
        // ---- stage V: gmem [t][d] -> smem [t][d] halfs ----
#pragma unroll
        for (int i = 0; i < 8; i++) {
            int idx = tid + i * NTHREADS;
            int t  = idx >> 4;
            int d4 = (idx & 15) * 4;
            float4 f = *reinterpret_cast<const float4*>(
                vbase + (size_t)(t0 + t) * D_ + d4);
            __half2 h0 = __floats2half2_rn(f.x, f.y);
            __half2 h1 = __floats2half2_rn(f.z, f.w);
            uint2 u; u.x = *(uint32_t*)&h0; u.y = *(uint32_t*)&h1;
            *reinterpret_cast<uint2*>(&Vs[t * KST + d4]) = u;
        }
        __syncthreads();

        // ---- GEMM1: S = Q @ K  (k = d, n = t) ----
        float s[2][8][4];
#pragma unroll
        for (int mt = 0; mt < 2; mt++)
#pragma unroll
            for (int nt = 0; nt < 8; nt++)
#pragma unroll
                for (int j = 0; j < 4; j++) s[mt][nt][j] = 0.0f;

#pragma unroll
        for (int kt = 0; kt < 4; kt++) {
#pragma unroll
            for (int np = 0; np < 4; np++) {
                uint32_t bfr[4];
                uint32_t a = smem_u32(
                    &Ks[(kt * 16 + ldrow) * KST + np * 16 + ldcol8]);
                ldsm_x4_t(bfr, a);
#pragma unroll
                for (int mt = 0; mt < 2; mt++) {
                    mma16816(s[mt][2 * np],     qa[mt][kt], bfr[0], bfr[1]);
                    mma16816(s[mt][2 * np + 1], qa[mt][kt], bfr[2], bfr[3]);
                }
            }
        }

        // ---- softmax (log2 domain), mask folded in ----
        // s-frag: [0]=(r,2c) [1]=(r,2c+1) [2]=(r+8,2c) [3]=(r+8,2c+1), col=2c+8nt
        float mk0[8], mk1[8];
#pragma unroll
        for (int nt = 0; nt < 8; nt++) {
            float2 mv = *reinterpret_cast<const float2*>(
                mbase + t0 + nt * 8 + 2 * (lane & 3));
            mk0[nt] = mv.x * LOG2E;
            mk1[nt] = mv.y * LOG2E;
        }
#pragma unroll
        for (int mt = 0; mt < 2; mt++) {
#pragma unroll
            for (int nt = 0; nt < 8; nt++) {
                s[mt][nt][0] = s[mt][nt][0] * SCALE_L2 + mk0[nt];
                s[mt][nt][1] = s[mt][nt][1] * SCALE_L2 + mk1[nt];
                s[mt][nt][2] = s[mt][nt][2] * SCALE_L2 + mk0[nt];
                s[mt][nt][3] = s[mt][nt][3] * SCALE_L2 + mk1[nt];
            }
#pragma unroll
            for (int h = 0; h < 2; h++) {   // row r (h=0) / r+8 (h=1)
                const int j0 = 2 * h;
                float mx = -1e30f;
#pragma unroll
                for (int nt = 0; nt < 8; nt++)
                    mx = fmaxf(mx, fmaxf(s[mt][nt][j0], s[mt][nt][j0 + 1]));
                mx = fmaxf(mx, __shfl_xor_sync(0xffffffffu, mx, 1));
                mx = fmaxf(mx, __shfl_xor_sync(0xffffffffu, mx, 2));

                float mnew = fmaxf(mrun[mt][h], mx);
                float corr = ex2(mrun[mt][h] - mnew);
                mrun[mt][h] = mnew;

                float psum = 0.0f;
#pragma unroll
                for (int nt = 0; nt < 8; nt++) {
                    float p0 = ex2(s[mt][nt][j0] - mnew);
                    float p1 = ex2(s[mt][nt][j0 + 1] - mnew);
                    s[mt][nt][j0] = p0;
                    s[mt][nt][j0 + 1] = p1;
                    psum += p0 + p1;
                }
                psum += __shfl_xor_sync(0xffffffffu, psum, 1);
                psum += __shfl_xor_sync(0xffffffffu, psum, 2);
                lrun[mt][h] = lrun[mt][h] * corr + psum;
#pragma unroll
                for (int nt = 0; nt < 8; nt++) {
                    o[mt][nt][j0] *= corr;
                    o[mt][nt][j0 + 1] *= corr;
                }
            }
        }

        // ---- pack P into A-fragments (pure register conversion) ----
        uint32_t pa[2][4][4];
#pragma unroll
        for (int mt = 0; mt < 2; mt++)
#pragma unroll
            for (int kt = 0; kt < 4; kt++) {
                __half2 h;
                h = __floats2half2_rn(s[mt][2 * kt][0], s[mt][2 * kt][1]);
                pa[mt][kt][0] = *(uint32_t*)&h;
                h = __floats2half2_rn(s[mt][2 * kt][2], s[mt][2 * kt][3]);
                pa[mt][kt][1] = *(uint32_t*)&h;
                h = __floats2half2_rn(s[mt][2 * kt + 1][0], s[mt][2 * kt + 1][1]);
                pa[mt][kt][2] = *(uint32_t*)&h;
                h = __floats2half2_rn(s[mt][2 * kt + 1][2], s[mt][2 * kt + 1][3]);
                pa[mt][kt][3] = *(uint32_t*)&h;
            }

        // ---- GEMM2: O += P @ V  (k = t, n = d) ----
#pragma unroll
        for (int kt = 0; kt < 4; kt++) {
#pragma unroll
            for (int np = 0; np < 4; np++) {
                uint32_t bfr[4];
                uint32_t a = smem_u32(
                    &Vs[(kt * 16 + ldrow) * KST + np * 16 + ldcol8]);
                ldsm_x4_t(bfr, a);
#pragma unroll
                for (int mt = 0; mt < 2; mt++) {
                    mma16816(o[mt][2 * np],     pa[mt][kt], bfr[0], bfr[1]);
                    mma16816(o[mt][2 * np + 1], pa[mt][kt], bfr[2], bfr[3]);
                }
            }
        }
    }

    // ---- epilogue: normalize & store f32 ----
#pragma unroll
    for (int mt = 0; mt < 2; mt++)
#pragma unroll
        for (int h = 0; h < 2; h++) {
            float inv = 1.0f / lrun[mt][h];
            int row = qrow0 + warp * 32 + mt * 16 + (lane >> 2) + 8 * h;
#pragma unroll
            for (int nt = 0; nt < 8; nt++) {
                float2 res;
                res.x = o[mt][nt][2 * h] * inv;
                res.y = o[mt][nt][2 * h + 1] * inv;
                *reinterpret_cast<float2*>(
                    out + ((size_t)bh * S_ + row) * D_ + nt * 8 + 2 * (lane & 3)) = res;
            }
        }
}

extern "C" void kernel_launch(void* const* d_in, const int* in_sizes, int n_in,
                              void* d_out, int out_size)
{
    const float* q    = (const float*)d_in[0];
    const float* k    = (const float*)d_in[1];
    const float* v    = (const float*)d_in[2];
    const float* mask = (const float*)d_in[3];
    float* out        = (float*)d_out;

    dim3 grid(S_ / BM, B_ * H_);
    attn_kernel<<<grid, NTHREADS>>>(q, k, v, mask, out);
}